// round 11
// baseline (speedup 1.0000x reference)
#include <cuda_runtime.h>
#include <stdint.h>

#define HW 512
#define PLANE (HW*HW)
#define TX 64
#define TY 32
#define NTHREADS 512
#define NT 2                 // tiles (batch images) per block
#define ZBLK 8               // blockIdx.z range; image b = z + tt*ZBLK
#define NBLOCKS (8*16*ZBLK)  // 1024

// gray = round(0.299R + 0.587G + 0.114B) in Q23 fixed point; coeffs sum to 2^23.
#define GC1 2508194u
#define GC2 4924113u
#define GC3 956301u
#define GRND (1u << 22)

__device__ unsigned long long g_sum_sobel;
__device__ unsigned long long g_sum_edge;
__device__ unsigned int       g_count;

// Inputs uniform [0,1): x*255 in [0,255) -> uint8 quantize == trunc toward 0.
__device__ __forceinline__ unsigned q8i(float x) { return (unsigned)(x * 255.0f); }

__device__ __forceinline__ unsigned gray1(unsigned R, unsigned G, unsigned B) {
    return (R * GC1 + G * GC2 + B * GC3 + GRND) >> 23;
}

// pack 4 byte-valued ints into one word via cvt.pack (cvt pipe, not ALU)
__device__ __forceinline__ unsigned packq(unsigned a0, unsigned a1,
                                          unsigned a2, unsigned a3) {
    unsigned t, d;
    asm("cvt.pack.sat.u8.s32.b32 %0, %1, %2, 0;"  : "=r"(t) : "r"(a3), "r"(a2));
    asm("cvt.pack.sat.u8.s32.b32 %0, %1, %2, %3;" : "=r"(d) : "r"(a1), "r"(a0), "r"(t));
    return d;
}

__global__ __launch_bounds__(NTHREADS, 2)
void cs_main_kernel(const float* __restrict__ pred, const float* __restrict__ tru,
                    float* __restrict__ out) {
    // gray: rows sy 0..35 (gy = y0-2+sy), cols 0..71 (gx = x0-4+sx), u8.
    // After phase 2 this storage is reused for the vertical-max (vm) plane.
    __shared__ unsigned char s_gray[2][36][72];
    // sobel: rows ry 0..33 (gy = y0-1+ry), 18 words per row
    __shared__ unsigned char s_sob[2][34][72];
    __shared__ unsigned int  s_red[32];

    const int tid = threadIdx.x;
    const int x0  = blockIdx.x * TX;
    const int y0  = blockIdx.y * TY;
    const int x04 = x0 >> 2;

    // Thread's own center word: cy 0..31, wc 0..15
    const int cy = tid >> 4;
    const int wc = tid & 15;
    const int tilebase = (y0 + cy) * HW + (x04 + wc) * 4;   // per-image offset

    // halo task coords (constant across tiles)
    int hsy, hv;
    if (tid < 72)       { const int r = tid / 18; hsy = (r < 2) ? r : r + 32; hv = tid - r * 18; }
    else if (tid < 136) { const int j = tid - 72; hsy = 2 + (j >> 1); hv = (j & 1) ? 17 : 0; }
    else                { hsy = 0; hv = 0; }
    const int hgy  = y0 - 2 + hsy;
    const int hgx4 = x04 - 1 + hv;
    const bool halo_ok = (tid < 136) && (hgy >= 0) && (hgy < HW) &&
                         (hgx4 >= 0) && (hgx4 < (HW / 4));
    const int halobase = hgy * HW + hgx4 * 4;

    const bool xl = (x0 == 0), xr = (x0 == HW - TX);
    const bool yt = (y0 == 0), yb = (y0 == HW - TY);
    const bool border = xl | xr | yt | yb;

    // ---- Prefetch tile 0 center words ----
    float4 pf[6];
    {
        const int base = blockIdx.z * 3 * PLANE + tilebase;
        pf[0] = *(const float4*)(pred + base);
        pf[1] = *(const float4*)(pred + base + PLANE);
        pf[2] = *(const float4*)(pred + base + 2 * PLANE);
        pf[3] = *(const float4*)(tru  + base);
        pf[4] = *(const float4*)(tru  + base + PLANE);
        pf[5] = *(const float4*)(tru  + base + 2 * PLANE);
    }

    unsigned acc_s = 0, acc_e = 0;

    #pragma unroll
    for (int tt = 0; tt < NT; tt++) {
        const int img_base = (blockIdx.z + tt * ZBLK) * 3 * PLANE;

        // ---- Phase 1a: convert prefetched center words; RGB kept in regs ----
        unsigned rgbw[6];
        #pragma unroll
        for (int im = 0; im < 2; im++) {
            const float4 A = pf[im * 3 + 0];
            const float4 B = pf[im * 3 + 1];
            const float4 C = pf[im * 3 + 2];
            const unsigned R0 = q8i(A.x), R1 = q8i(A.y), R2 = q8i(A.z), R3 = q8i(A.w);
            const unsigned G0 = q8i(B.x), G1 = q8i(B.y), G2 = q8i(B.z), G3 = q8i(B.w);
            const unsigned B0 = q8i(C.x), B1 = q8i(C.y), B2 = q8i(C.z), B3 = q8i(C.w);
            rgbw[im * 3 + 0] = packq(R0, R1, R2, R3);
            rgbw[im * 3 + 1] = packq(G0, G1, G2, G3);
            rgbw[im * 3 + 2] = packq(B0, B1, B2, B3);
            *(unsigned int*)&s_gray[im][cy + 2][(wc + 1) * 4] =
                packq(gray1(R0, G0, B0), gray1(R1, G1, B1),
                      gray1(R2, G2, B2), gray1(R3, G3, B3));
        }

        // ---- Phase 1b: halo words (gray only) ----
        if (halo_ok) {
            const int base = img_base + halobase;
            #pragma unroll
            for (int im = 0; im < 2; im++) {
                const float* src = im ? tru : pred;
                float4 A = *(const float4*)(src + base);
                float4 B = *(const float4*)(src + base + PLANE);
                float4 C = *(const float4*)(src + base + 2 * PLANE);
                *(unsigned int*)&s_gray[im][hsy][hv * 4] =
                    packq(gray1(q8i(A.x), q8i(B.x), q8i(C.x)),
                          gray1(q8i(A.y), q8i(B.y), q8i(C.y)),
                          gray1(q8i(A.z), q8i(B.z), q8i(C.z)),
                          gray1(q8i(A.w), q8i(B.w), q8i(C.w)));
            }
        }

        // ---- Border mirror fixups (reflect-101, halo <= 2) ----
        if (border) {
            __syncthreads();
            if (tid < 72) {                        // column mirror, per (img,row)
                const int im = tid >= 36; const int sy = tid - im * 36;
                if (xl) { s_gray[im][sy][2]  = s_gray[im][sy][6];
                          s_gray[im][sy][3]  = s_gray[im][sy][5]; }
                if (xr) { s_gray[im][sy][68] = s_gray[im][sy][66];
                          s_gray[im][sy][69] = s_gray[im][sy][65]; }
            }
            __syncthreads();
            if (tid < 72) {                        // row mirror (full 18-word rows)
                const int w = tid % 18; const int r = tid / 18;
                const int im = r >> 1; const int which = r & 1;
                if (yt) {
                    const int dst = which ? 1 : 0, src = which ? 3 : 4;
                    *(unsigned int*)&s_gray[im][dst][w * 4] =
                        *(unsigned int*)&s_gray[im][src][w * 4];
                }
                if (yb) {
                    const int dst = which ? (TY + 3) : (TY + 2);
                    const int src = which ? (TY - 1) : TY;
                    *(unsigned int*)&s_gray[im][dst][w * 4] =
                        *(unsigned int*)&s_gray[im][src][w * 4];
                }
            }
        }
        __syncthreads();

        // ---- Prefetch next tile's center words (overlaps phases 2..3) ----
        if (tt + 1 < NT) {
            const int nbase = (blockIdx.z + (tt + 1) * ZBLK) * 3 * PLANE + tilebase;
            pf[0] = *(const float4*)(pred + nbase);
            pf[1] = *(const float4*)(pred + nbase + PLANE);
            pf[2] = *(const float4*)(pred + nbase + 2 * PLANE);
            pf[3] = *(const float4*)(tru  + nbase);
            pf[4] = *(const float4*)(tru  + nbase + PLANE);
            pf[5] = *(const float4*)(tru  + nbase + 2 * PLANE);
        }

        // ---- Phase 2: SIMD byte sobel (exact half-even via vavg + fix) ----
        for (int t = tid; t < 34 * 18 * 2; t += NTHREADS) {
            const int im = t >= 34 * 18;
            const int r  = t - im * 34 * 18;
            const int ry = r / 18;
            const int w  = r - ry * 18;          // 0..17
            const unsigned char* gr = &s_gray[im][0][0];
            const int off = (ry + 1) * 72 + w * 4;
            const unsigned cur = *(const unsigned int*)(gr + off);
            const unsigned prv = *(const unsigned int*)(gr + off - 4);
            const unsigned nxt = *(const unsigned int*)(gr + off + 4);
            const unsigned N4  = *(const unsigned int*)(gr + off - 72);
            const unsigned S4  = *(const unsigned int*)(gr + off + 72);
            const unsigned E4  = __funnelshift_r(cur, nxt, 8);
            const unsigned W4  = __funnelshift_r(prv, cur, 24);
            const unsigned sx4 = __vabsdiffu4(E4, W4);
            const unsigned sy4 = __vabsdiffu4(S4, N4);
            const unsigned avg = __vavgu4(sx4, sy4);
            const unsigned cor = (sx4 ^ sy4) & avg & 0x01010101u;
            *(unsigned int*)&s_sob[im][ry][w * 4] = avg - cor;
        }
        __syncthreads();

        // ---- Phase 2b: vertical 3-row byte max (overwrites dead s_gray) ----
        unsigned char (*s_vm)[72] = (unsigned char (*)[72])&s_gray[0][0][0];
        for (int t = tid; t < TY * 18 * 2; t += NTHREADS) {
            const int im = t >= TY * 18;
            const int r  = t - im * TY * 18;
            const int py = r / 18;
            const int w  = r - py * 18;
            const int ry = py + 1;
            const unsigned a = *(const unsigned int*)&s_sob[im][ry - 1][w * 4];
            const unsigned c = *(const unsigned int*)&s_sob[im][ry    ][w * 4];
            const unsigned d = *(const unsigned int*)&s_sob[im][ry + 1][w * 4];
            *(unsigned int*)&s_vm[im * TY + py][w * 4] = __vmaxu4(a, __vmaxu4(c, d));
        }
        __syncthreads();

        // ---- Phase 3: losses (one center word per thread) ----
        {
            const int py = cy;
            const int w  = wc + 1;
            const unsigned sp4 = *(const unsigned int*)&s_sob[0][py + 1][w * 4];
            const unsigned st4 = *(const unsigned int*)&s_sob[1][py + 1][w * 4];
            acc_s = __dp4a(__vabsdiffu4(sp4, st4), 0x01010101u, acc_s);

            unsigned k[2];
            #pragma unroll
            for (int im = 0; im < 2; im++) {
                const unsigned char* vr = &s_vm[im * TY + py][0];
                const unsigned p = *(const unsigned int*)(vr + w * 4 - 4);
                const unsigned c = *(const unsigned int*)(vr + w * 4);
                const unsigned n = *(const unsigned int*)(vr + w * 4 + 4);
                const unsigned mx = __vmaxu4(c,
                    __vmaxu4(__funnelshift_r(p, c, 24), __funnelshift_r(c, n, 8)));
                k[im] = __vcmpgtu4(mx, 0x0A0A0A0Au);
            }
            const unsigned both = k[0] & k[1];
            const unsigned onp  = k[0] & ~k[1];
            const unsigned ont  = k[1] & ~k[0];
            #pragma unroll
            for (int ch = 0; ch < 3; ch++) {
                const unsigned pw = rgbw[ch];
                const unsigned tw = rgbw[3 + ch];
                const unsigned val = (__vabsdiffu4(pw, tw) & both) |
                                     (pw & onp) | (tw & ont);
                acc_e = __dp4a(val, 0x01010101u, acc_e);
            }
        }
        if (tt + 1 < NT) __syncthreads();   // protect s_gray/s_sob reuse
    }

    // ---- Phase 4: exact integer reduction + last-block finalize ----
    unsigned ws = __reduce_add_sync(0xFFFFFFFFu, acc_s);
    unsigned we = __reduce_add_sync(0xFFFFFFFFu, acc_e);
    const int warp = tid >> 5, lane = tid & 31;
    if (lane == 0) { s_red[warp] = ws; s_red[16 + warp] = we; }
    __syncthreads();
    if (warp == 0) {
        unsigned a = (lane < 16) ? s_red[lane] : 0u;
        unsigned e = (lane < 16) ? s_red[16 + lane] : 0u;
        a = __reduce_add_sync(0xFFFFFFFFu, a);
        e = __reduce_add_sync(0xFFFFFFFFu, e);
        if (lane == 0) {
            atomicAdd(&g_sum_sobel, (unsigned long long)a);
            atomicAdd(&g_sum_edge,  (unsigned long long)e);
            __threadfence();
            const unsigned old = atomicAdd(&g_count, 1u);
            if (old == NBLOCKS - 1) {
                const unsigned long long ss = atomicAdd(&g_sum_sobel, 0ULL);
                const unsigned long long se = atomicAdd(&g_sum_edge, 0ULL);
                const double N = 16.0 * 512.0 * 512.0;
                out[0] = (float)((double)ss / (255.0 * N));
                out[1] = (float)((double)se / (255.0 * N * 3.0));
                g_sum_sobel = 0ULL;
                g_sum_edge  = 0ULL;
                __threadfence();
                g_count = 0u;
            }
        }
    }
}

extern "C" void kernel_launch(void* const* d_in, const int* in_sizes, int n_in,
                              void* d_out, int out_size) {
    const float* y_pred = (const float*)d_in[0];
    const float* y_true = (const float*)d_in[1];
    float* out = (float*)d_out;

    dim3 grid(HW / TX, HW / TY, ZBLK);
    cs_main_kernel<<<grid, NTHREADS>>>(y_pred, y_true, out);
}

// round 12
// speedup vs baseline: 1.0749x; 1.0749x over previous
#include <cuda_runtime.h>
#include <stdint.h>

#define HW 512
#define PLANE (HW*HW)
#define SH 16                 // output rows per warp strip
#define NTHREADS 256
#define NWARPS 8
#define NBLOCKS 320           // 2560 warp tasks / 8

// gray = round(0.299R + 0.587G + 0.114B) in Q23 fixed point; coeffs sum to 2^23.
#define GC1 2508194u
#define GC2 4924113u
#define GC3 956301u
#define GRND (1u << 22)

__device__ unsigned long long g_sum_sobel;
__device__ unsigned long long g_sum_edge;
__device__ unsigned int       g_count;

// Inputs uniform [0,1): x*255 in [0,255) -> uint8 quantize == trunc toward 0.
__device__ __forceinline__ unsigned q8i(float x) { return (unsigned)(x * 255.0f); }

__device__ __forceinline__ unsigned gray1(unsigned R, unsigned G, unsigned B) {
    return (R * GC1 + G * GC2 + B * GC3 + GRND) >> 23;
}

// pack 4 byte-valued ints into one word via cvt.pack (cvt pipe, not ALU)
__device__ __forceinline__ unsigned packq(unsigned a0, unsigned a1,
                                          unsigned a2, unsigned a3) {
    unsigned t, d;
    asm("cvt.pack.sat.u8.s32.b32 %0, %1, %2, 0;"  : "=r"(t) : "r"(a3), "r"(a2));
    asm("cvt.pack.sat.u8.s32.b32 %0, %1, %2, %3;" : "=r"(d) : "r"(a1), "r"(a0), "r"(t));
    return d;
}

__device__ __forceinline__ int reflect512(int i) {
    i = i < 0 ? -i : i;
    return i > 511 ? 1022 - i : i;
}

__global__ __launch_bounds__(NTHREADS)
void cs_main_kernel(const float* __restrict__ pred, const float* __restrict__ tru,
                    float* __restrict__ out)
{
    __shared__ unsigned s_red[16];

    const int tid  = threadIdx.x;
    const int lane = tid & 31;
    const int wid  = tid >> 5;
    const int task = blockIdx.x * NWARPS + wid;   // 0..2559
    const int sx   = task % 5;                    // x strip 0..4
    const int rg   = (task / 5) & 31;             // row group 0..31
    const int img  = task / 160;                  // image 0..15
    const int r0   = rg * SH;

    // lane -> packed word index (4 px). Lanes 0 and 31 are halo-only.
    const int word = 30 * sx - 1 + lane;
    const bool ld_ok  = ((unsigned)word <= 127u);
    const bool out_ok = (lane >= 1) && (lane <= 30) && ((unsigned)word <= 127u);
    const bool wedge  = (sx == 0) && (lane == 1);       // image left edge word
    const bool eedge  = (sx == 4) && (word == 127);     // image right edge word

    const float* pb = pred + img * 3 * PLANE + word * 4;
    const float* tb = tru  + img * 3 * PLANE + word * 4;

    auto loadrow = [&](int j, float4* F) {
        const int gy = reflect512(r0 - 2 + j);
        const float* p = pb + gy * HW;
        const float* t = tb + gy * HW;
        if (ld_ok) {
            F[0] = *(const float4*)(p);
            F[1] = *(const float4*)(p + PLANE);
            F[2] = *(const float4*)(p + 2 * PLANE);
            F[3] = *(const float4*)(t);
            F[4] = *(const float4*)(t + PLANE);
            F[5] = *(const float4*)(t + 2 * PLANE);
        }
    };

    auto convrow = [&](const float4* F, unsigned& gP, unsigned& gT,
                       unsigned* rP, unsigned* rT) {
        {
            unsigned R0=q8i(F[0].x),R1=q8i(F[0].y),R2=q8i(F[0].z),R3=q8i(F[0].w);
            unsigned G0=q8i(F[1].x),G1=q8i(F[1].y),G2=q8i(F[1].z),G3=q8i(F[1].w);
            unsigned B0=q8i(F[2].x),B1=q8i(F[2].y),B2=q8i(F[2].z),B3=q8i(F[2].w);
            rP[0]=packq(R0,R1,R2,R3); rP[1]=packq(G0,G1,G2,G3); rP[2]=packq(B0,B1,B2,B3);
            gP = packq(gray1(R0,G0,B0), gray1(R1,G1,B1),
                       gray1(R2,G2,B2), gray1(R3,G3,B3));
        }
        {
            unsigned R0=q8i(F[3].x),R1=q8i(F[3].y),R2=q8i(F[3].z),R3=q8i(F[3].w);
            unsigned G0=q8i(F[4].x),G1=q8i(F[4].y),G2=q8i(F[4].z),G3=q8i(F[4].w);
            unsigned B0=q8i(F[5].x),B1=q8i(F[5].y),B2=q8i(F[5].z),B3=q8i(F[5].w);
            rT[0]=packq(R0,R1,R2,R3); rT[1]=packq(G0,G1,G2,G3); rT[2]=packq(B0,B1,B2,B3);
            gT = packq(gray1(R0,G0,B0), gray1(R1,G1,B1),
                       gray1(R2,G2,B2), gray1(R3,G3,B3));
        }
    };

    // sobel of the row held in gmid (gup/gdn: rows above/below), exact half-even.
    auto sobelrow = [&](unsigned gup, unsigned gmid, unsigned gdn) -> unsigned {
        const unsigned gp = __shfl_up_sync(0xFFFFFFFFu, gmid, 1);
        const unsigned gn = __shfl_down_sync(0xFFFFFFFFu, gmid, 1);
        unsigned W4 = __funnelshift_r(gp, gmid, 24);
        unsigned E4 = __funnelshift_r(gmid, gn, 8);
        if (wedge) W4 = __byte_perm(gmid, 0, 0x2101);   // reflect at x=0
        if (eedge) E4 = __byte_perm(gmid, 0, 0x2321);   // reflect at x=511
        const unsigned sx4 = __vabsdiffu4(E4, W4);
        const unsigned sy4 = __vabsdiffu4(gdn, gup);
        const unsigned avg = __vavgu4(sx4, sy4);
        const unsigned cor = (sx4 ^ sy4) & avg & 0x01010101u;
        return avg - cor;
    };

    auto dilmask = [&](unsigned vm) -> unsigned {
        const unsigned vp = __shfl_up_sync(0xFFFFFFFFu, vm, 1);
        const unsigned vn = __shfl_down_sync(0xFFFFFFFFu, vm, 1);
        unsigned Wv = __funnelshift_r(vp, vm, 24);
        unsigned Ev = __funnelshift_r(vm, vn, 8);
        if (wedge) Wv = __byte_perm(vm, 0, 0x2101);
        if (eedge) Ev = __byte_perm(vm, 0, 0x2321);
        return __vcmpgtu4(__vmaxu4(vm, __vmaxu4(Wv, Ev)), 0x0A0A0A0Au);
    };

    float4 Fc[6], Fn[6];
    unsigned gp1, gp2, gt1, gt2;         // gray rows j-2, j-1
    unsigned sp1, sp2, st1, st2;         // sobel rows j-3, j-2
    unsigned rpA[3], rpB[3], rpC[3];     // rgb pred rows j, j-1, j-2
    unsigned rtA[3], rtB[3], rtC[3];
    unsigned acc_s = 0, acc_e = 0;

    // ---- prologue: rows 0,1 ----
    loadrow(0, Fc);
    loadrow(1, Fn);
    convrow(Fc, gp1, gt1, rpC, rtC);                  // row 0
    #pragma unroll
    for (int q = 0; q < 6; q++) Fc[q] = Fn[q];
    loadrow(2, Fn);
    convrow(Fc, gp2, gt2, rpB, rtB);                  // row 1
    #pragma unroll
    for (int q = 0; q < 6; q++) Fc[q] = Fn[q];        // Fc = row 2

    // ---- j = 2,3: build sobel ring, no loss yet ----
    #pragma unroll
    for (int j = 2; j <= 3; ++j) {
        loadrow(j + 1, Fn);
        unsigned gnp, gnt;
        convrow(Fc, gnp, gnt, rpA, rtA);              // row j
        const unsigned snp = sobelrow(gp1, gp2, gnp); // sobel row j-1
        const unsigned snt = sobelrow(gt1, gt2, gnt);
        sp1 = sp2; sp2 = snp; st1 = st2; st2 = snt;
        gp1 = gp2; gp2 = gnp; gt1 = gt2; gt2 = gnt;
        #pragma unroll
        for (int c = 0; c < 3; c++) {
            rpC[c] = rpB[c]; rpB[c] = rpA[c];
            rtC[c] = rtB[c]; rtB[c] = rtA[c];
        }
        #pragma unroll
        for (int q = 0; q < 6; q++) Fc[q] = Fn[q];
    }

    // ---- steady loop: j = 4 .. SH+3, loss for image row r0 + j - 4 ----
    #pragma unroll 2
    for (int j = 4; j <= SH + 3; ++j) {
        if (j < SH + 3) loadrow(j + 1, Fn);
        unsigned gnp, gnt;
        convrow(Fc, gnp, gnt, rpA, rtA);              // row j
        const unsigned snp = sobelrow(gp1, gp2, gnp); // sobel row j-1
        const unsigned snt = sobelrow(gt1, gt2, gnt);
        // vm row j-2 = max(sobel rows j-3, j-2, j-1)
        const unsigned vmp = __vmaxu4(sp1, __vmaxu4(sp2, snp));
        const unsigned vmt = __vmaxu4(st1, __vmaxu4(st2, snt));
        const unsigned kp = dilmask(vmp);
        const unsigned kt = dilmask(vmt);
        if (out_ok) {
            acc_s = __dp4a(__vabsdiffu4(sp2, st2), 0x01010101u, acc_s);
            const unsigned both = kp & kt;
            const unsigned onp  = kp & ~kt;
            const unsigned ont  = kt & ~kp;
            #pragma unroll
            for (int c = 0; c < 3; c++) {
                const unsigned val = (__vabsdiffu4(rpC[c], rtC[c]) & both) |
                                     (rpC[c] & onp) | (rtC[c] & ont);
                acc_e = __dp4a(val, 0x01010101u, acc_e);
            }
        }
        sp1 = sp2; sp2 = snp; st1 = st2; st2 = snt;
        gp1 = gp2; gp2 = gnp; gt1 = gt2; gt2 = gnt;
        #pragma unroll
        for (int c = 0; c < 3; c++) {
            rpC[c] = rpB[c]; rpB[c] = rpA[c];
            rtC[c] = rtB[c]; rtB[c] = rtA[c];
        }
        #pragma unroll
        for (int q = 0; q < 6; q++) Fc[q] = Fn[q];
    }

    // ---- exact integer reduction + last-block finalize ----
    const unsigned ws = __reduce_add_sync(0xFFFFFFFFu, acc_s);
    const unsigned we = __reduce_add_sync(0xFFFFFFFFu, acc_e);
    if (lane == 0) { s_red[wid] = ws; s_red[8 + wid] = we; }
    __syncthreads();
    if (wid == 0) {
        unsigned a = (lane < 8) ? s_red[lane] : 0u;
        unsigned e = (lane < 8) ? s_red[8 + lane] : 0u;
        a = __reduce_add_sync(0xFFFFFFFFu, a);
        e = __reduce_add_sync(0xFFFFFFFFu, e);
        if (lane == 0) {
            atomicAdd(&g_sum_sobel, (unsigned long long)a);
            atomicAdd(&g_sum_edge,  (unsigned long long)e);
            __threadfence();
            const unsigned old = atomicAdd(&g_count, 1u);
            if (old == NBLOCKS - 1) {
                const unsigned long long ss = atomicAdd(&g_sum_sobel, 0ULL);
                const unsigned long long se = atomicAdd(&g_sum_edge, 0ULL);
                const double N = 16.0 * 512.0 * 512.0;
                out[0] = (float)((double)ss / (255.0 * N));
                out[1] = (float)((double)se / (255.0 * N * 3.0));
                g_sum_sobel = 0ULL;
                g_sum_edge  = 0ULL;
                __threadfence();
                g_count = 0u;
            }
        }
    }
}

extern "C" void kernel_launch(void* const* d_in, const int* in_sizes, int n_in,
                              void* d_out, int out_size) {
    const float* y_pred = (const float*)d_in[0];
    const float* y_true = (const float*)d_in[1];
    float* out = (float*)d_out;

    cs_main_kernel<<<NBLOCKS, NTHREADS>>>(y_pred, y_true, out);
}

// round 13
// speedup vs baseline: 1.1593x; 1.0785x over previous
#include <cuda_runtime.h>
#include <stdint.h>

#define HW 512
#define PLANE (HW*HW)
#define SH 16                 // output rows per warp strip
#define NTHREADS 64
#define NWARPS 2
#define NBLOCKS 1280          // 2560 warp tasks / 2

// gray = round(0.299R + 0.587G + 0.114B) in Q23 fixed point; coeffs sum to 2^23.
#define GC1 2508194u
#define GC2 4924113u
#define GC3 956301u
#define GRND (1u << 22)

__device__ unsigned long long g_sum_sobel;
__device__ unsigned long long g_sum_edge;
__device__ unsigned int       g_count;

// Inputs uniform [0,1): x*255 in [0,255) -> uint8 quantize == trunc toward 0.
__device__ __forceinline__ unsigned q8i(float x) { return (unsigned)(x * 255.0f); }

__device__ __forceinline__ unsigned gray1(unsigned R, unsigned G, unsigned B) {
    return (R * GC1 + G * GC2 + B * GC3 + GRND) >> 23;
}

// pack 4 byte-valued ints into one word via cvt.pack (cvt pipe, not ALU)
__device__ __forceinline__ unsigned packq(unsigned a0, unsigned a1,
                                          unsigned a2, unsigned a3) {
    unsigned t, d;
    asm("cvt.pack.sat.u8.s32.b32 %0, %1, %2, 0;"  : "=r"(t) : "r"(a3), "r"(a2));
    asm("cvt.pack.sat.u8.s32.b32 %0, %1, %2, %3;" : "=r"(d) : "r"(a1), "r"(a0), "r"(t));
    return d;
}

__device__ __forceinline__ int reflect512(int i) {
    i = i < 0 ? -i : i;
    return i > 511 ? 1022 - i : i;
}

__global__ __launch_bounds__(NTHREADS)
void cs_main_kernel(const float* __restrict__ pred, const float* __restrict__ tru,
                    float* __restrict__ out)
{
    __shared__ unsigned s_red[2 * NWARPS];

    const int tid  = threadIdx.x;
    const int lane = tid & 31;
    const int wid  = tid >> 5;
    const int task = blockIdx.x * NWARPS + wid;   // 0..2559
    const int sx   = task % 5;                    // x strip 0..4
    const int rg   = (task / 5) & 31;             // row group 0..31
    const int img  = task / 160;                  // image 0..15
    const int r0   = rg * SH;

    // lane -> packed word index (4 px). Lanes 0 and 31 are halo-only.
    const int word = 30 * sx - 1 + lane;
    const bool ld_ok  = ((unsigned)word <= 127u);
    const bool out_ok = (lane >= 1) && (lane <= 30) && ((unsigned)word <= 127u);
    const bool wedge  = (sx == 0) && (lane == 1);       // image left edge word
    const bool eedge  = (sx == 4) && (word == 127);     // image right edge word

    const float* pb = pred + img * 3 * PLANE + word * 4;
    const float* tb = tru  + img * 3 * PLANE + word * 4;

    auto loadrow = [&](int j, float4* F) {
        const int gy = reflect512(r0 - 2 + j);
        const float* p = pb + gy * HW;
        const float* t = tb + gy * HW;
        if (ld_ok) {
            F[0] = *(const float4*)(p);
            F[1] = *(const float4*)(p + PLANE);
            F[2] = *(const float4*)(p + 2 * PLANE);
            F[3] = *(const float4*)(t);
            F[4] = *(const float4*)(t + PLANE);
            F[5] = *(const float4*)(t + 2 * PLANE);
        }
    };

    auto convrow = [&](const float4* F, unsigned& gP, unsigned& gT,
                       unsigned* rP, unsigned* rT) {
        {
            unsigned R0=q8i(F[0].x),R1=q8i(F[0].y),R2=q8i(F[0].z),R3=q8i(F[0].w);
            unsigned G0=q8i(F[1].x),G1=q8i(F[1].y),G2=q8i(F[1].z),G3=q8i(F[1].w);
            unsigned B0=q8i(F[2].x),B1=q8i(F[2].y),B2=q8i(F[2].z),B3=q8i(F[2].w);
            rP[0]=packq(R0,R1,R2,R3); rP[1]=packq(G0,G1,G2,G3); rP[2]=packq(B0,B1,B2,B3);
            gP = packq(gray1(R0,G0,B0), gray1(R1,G1,B1),
                       gray1(R2,G2,B2), gray1(R3,G3,B3));
        }
        {
            unsigned R0=q8i(F[3].x),R1=q8i(F[3].y),R2=q8i(F[3].z),R3=q8i(F[3].w);
            unsigned G0=q8i(F[4].x),G1=q8i(F[4].y),G2=q8i(F[4].z),G3=q8i(F[4].w);
            unsigned B0=q8i(F[5].x),B1=q8i(F[5].y),B2=q8i(F[5].z),B3=q8i(F[5].w);
            rT[0]=packq(R0,R1,R2,R3); rT[1]=packq(G0,G1,G2,G3); rT[2]=packq(B0,B1,B2,B3);
            gT = packq(gray1(R0,G0,B0), gray1(R1,G1,B1),
                       gray1(R2,G2,B2), gray1(R3,G3,B3));
        }
    };

    // sobel of the row held in gmid (gup/gdn: rows above/below), exact half-even.
    auto sobelrow = [&](unsigned gup, unsigned gmid, unsigned gdn) -> unsigned {
        const unsigned gp = __shfl_up_sync(0xFFFFFFFFu, gmid, 1);
        const unsigned gn = __shfl_down_sync(0xFFFFFFFFu, gmid, 1);
        unsigned W4 = __funnelshift_r(gp, gmid, 24);
        unsigned E4 = __funnelshift_r(gmid, gn, 8);
        if (wedge) W4 = __byte_perm(gmid, 0, 0x2101);   // reflect at x=0
        if (eedge) E4 = __byte_perm(gmid, 0, 0x2321);   // reflect at x=511
        const unsigned sx4 = __vabsdiffu4(E4, W4);
        const unsigned sy4 = __vabsdiffu4(gdn, gup);
        const unsigned avg = __vavgu4(sx4, sy4);
        const unsigned cor = (sx4 ^ sy4) & avg & 0x01010101u;
        return avg - cor;
    };

    auto dilmask = [&](unsigned vm) -> unsigned {
        const unsigned vp = __shfl_up_sync(0xFFFFFFFFu, vm, 1);
        const unsigned vn = __shfl_down_sync(0xFFFFFFFFu, vm, 1);
        unsigned Wv = __funnelshift_r(vp, vm, 24);
        unsigned Ev = __funnelshift_r(vm, vn, 8);
        if (wedge) Wv = __byte_perm(vm, 0, 0x2101);
        if (eedge) Ev = __byte_perm(vm, 0, 0x2321);
        return __vcmpgtu4(__vmaxu4(vm, __vmaxu4(Wv, Ev)), 0x0A0A0A0Au);
    };

    float4 Fc[6], Fn[6];
    unsigned gp1, gp2, gt1, gt2;         // gray rows j-2, j-1
    unsigned sp1, sp2, st1, st2;         // sobel rows j-3, j-2
    unsigned rpA[3], rpB[3], rpC[3];     // rgb pred rows j, j-1, j-2
    unsigned rtA[3], rtB[3], rtC[3];
    unsigned acc_s = 0, acc_e = 0;

    // ---- prologue: rows 0,1 ----
    loadrow(0, Fc);
    loadrow(1, Fn);
    convrow(Fc, gp1, gt1, rpC, rtC);                  // row 0
    #pragma unroll
    for (int q = 0; q < 6; q++) Fc[q] = Fn[q];
    loadrow(2, Fn);
    convrow(Fc, gp2, gt2, rpB, rtB);                  // row 1
    #pragma unroll
    for (int q = 0; q < 6; q++) Fc[q] = Fn[q];        // Fc = row 2

    // ---- j = 2,3: build sobel ring, no loss yet ----
    #pragma unroll
    for (int j = 2; j <= 3; ++j) {
        loadrow(j + 1, Fn);
        unsigned gnp, gnt;
        convrow(Fc, gnp, gnt, rpA, rtA);              // row j
        const unsigned snp = sobelrow(gp1, gp2, gnp); // sobel row j-1
        const unsigned snt = sobelrow(gt1, gt2, gnt);
        sp1 = sp2; sp2 = snp; st1 = st2; st2 = snt;
        gp1 = gp2; gp2 = gnp; gt1 = gt2; gt2 = gnt;
        #pragma unroll
        for (int c = 0; c < 3; c++) {
            rpC[c] = rpB[c]; rpB[c] = rpA[c];
            rtC[c] = rtB[c]; rtB[c] = rtA[c];
        }
        #pragma unroll
        for (int q = 0; q < 6; q++) Fc[q] = Fn[q];
    }

    // ---- steady loop: j = 4 .. SH+3, loss for image row r0 + j - 4 ----
    #pragma unroll 2
    for (int j = 4; j <= SH + 3; ++j) {
        if (j < SH + 3) loadrow(j + 1, Fn);
        unsigned gnp, gnt;
        convrow(Fc, gnp, gnt, rpA, rtA);              // row j
        const unsigned snp = sobelrow(gp1, gp2, gnp); // sobel row j-1
        const unsigned snt = sobelrow(gt1, gt2, gnt);
        // vm row j-2 = max(sobel rows j-3, j-2, j-1)
        const unsigned vmp = __vmaxu4(sp1, __vmaxu4(sp2, snp));
        const unsigned vmt = __vmaxu4(st1, __vmaxu4(st2, snt));
        const unsigned kp = dilmask(vmp);
        const unsigned kt = dilmask(vmt);
        if (out_ok) {
            acc_s = __dp4a(__vabsdiffu4(sp2, st2), 0x01010101u, acc_s);
            const unsigned both = kp & kt;
            const unsigned onp  = kp & ~kt;
            const unsigned ont  = kt & ~kp;
            #pragma unroll
            for (int c = 0; c < 3; c++) {
                const unsigned val = (__vabsdiffu4(rpC[c], rtC[c]) & both) |
                                     (rpC[c] & onp) | (rtC[c] & ont);
                acc_e = __dp4a(val, 0x01010101u, acc_e);
            }
        }
        sp1 = sp2; sp2 = snp; st1 = st2; st2 = snt;
        gp1 = gp2; gp2 = gnp; gt1 = gt2; gt2 = gnt;
        #pragma unroll
        for (int c = 0; c < 3; c++) {
            rpC[c] = rpB[c]; rpB[c] = rpA[c];
            rtC[c] = rtB[c]; rtB[c] = rtA[c];
        }
        #pragma unroll
        for (int q = 0; q < 6; q++) Fc[q] = Fn[q];
    }

    // ---- exact integer reduction + last-block finalize ----
    const unsigned ws = __reduce_add_sync(0xFFFFFFFFu, acc_s);
    const unsigned we = __reduce_add_sync(0xFFFFFFFFu, acc_e);
    if (lane == 0) { s_red[wid] = ws; s_red[NWARPS + wid] = we; }
    __syncthreads();
    if (wid == 0) {
        unsigned a = (lane < NWARPS) ? s_red[lane] : 0u;
        unsigned e = (lane < NWARPS) ? s_red[NWARPS + lane] : 0u;
        a = __reduce_add_sync(0xFFFFFFFFu, a);
        e = __reduce_add_sync(0xFFFFFFFFu, e);
        if (lane == 0) {
            atomicAdd(&g_sum_sobel, (unsigned long long)a);
            atomicAdd(&g_sum_edge,  (unsigned long long)e);
            __threadfence();
            const unsigned old = atomicAdd(&g_count, 1u);
            if (old == NBLOCKS - 1) {
                const unsigned long long ss = atomicAdd(&g_sum_sobel, 0ULL);
                const unsigned long long se = atomicAdd(&g_sum_edge, 0ULL);
                const double N = 16.0 * 512.0 * 512.0;
                out[0] = (float)((double)ss / (255.0 * N));
                out[1] = (float)((double)se / (255.0 * N * 3.0));
                g_sum_sobel = 0ULL;
                g_sum_edge  = 0ULL;
                __threadfence();
                g_count = 0u;
            }
        }
    }
}

extern "C" void kernel_launch(void* const* d_in, const int* in_sizes, int n_in,
                              void* d_out, int out_size) {
    const float* y_pred = (const float*)d_in[0];
    const float* y_true = (const float*)d_in[1];
    float* out = (float*)d_out;

    cs_main_kernel<<<NBLOCKS, NTHREADS>>>(y_pred, y_true, out);
}

// round 14
// speedup vs baseline: 1.2358x; 1.0660x over previous
#include <cuda_runtime.h>
#include <stdint.h>

#define HW 512
#define PLANE (HW*HW)
#define SH 16                 // output rows per warp strip
#define NTHREADS 64
#define NWARPS 2
#define NBLOCKS 1280          // 2560 warp tasks / 2

// gray = round(0.299R + 0.587G + 0.114B) in Q23 fixed point; coeffs sum to 2^23.
#define GC1 2508194u
#define GC2 4924113u
#define GC3 956301u
#define GRND (1u << 22)

__device__ unsigned long long g_sum_sobel;
__device__ unsigned long long g_sum_edge;
__device__ unsigned int       g_count;

// Inputs uniform [0,1): x*255 in [0,255) -> uint8 quantize == trunc toward 0.
__device__ __forceinline__ unsigned q8i(float x) { return (unsigned)(x * 255.0f); }

__device__ __forceinline__ unsigned gray1(unsigned R, unsigned G, unsigned B) {
    return (R * GC1 + G * GC2 + B * GC3 + GRND) >> 23;
}

// pack 4 byte-valued ints into one word via cvt.pack (cvt pipe, not ALU)
__device__ __forceinline__ unsigned packq(unsigned a0, unsigned a1,
                                          unsigned a2, unsigned a3) {
    unsigned t, d;
    asm("cvt.pack.sat.u8.s32.b32 %0, %1, %2, 0;"  : "=r"(t) : "r"(a3), "r"(a2));
    asm("cvt.pack.sat.u8.s32.b32 %0, %1, %2, %3;" : "=r"(d) : "r"(a1), "r"(a0), "r"(t));
    return d;
}

__device__ __forceinline__ int reflect512(int i) {
    i = i < 0 ? -i : i;
    return i > 511 ? 1022 - i : i;
}

__global__ __launch_bounds__(NTHREADS, 10)
void cs_main_kernel(const float* __restrict__ pred, const float* __restrict__ tru,
                    float* __restrict__ out)
{
    __shared__ unsigned s_red[2 * NWARPS];

    const int tid  = threadIdx.x;
    const int lane = tid & 31;
    const int wid  = tid >> 5;
    const int task = blockIdx.x * NWARPS + wid;   // 0..2559
    const int sx   = task % 5;                    // x strip 0..4
    const int rg   = (task / 5) & 31;             // row group 0..31
    const int img  = task / 160;                  // image 0..15
    const int r0   = rg * SH;

    // lane -> packed word index (4 px). Lanes 0 and 31 are halo-only.
    const int word = 30 * sx - 1 + lane;
    const bool ld_ok  = ((unsigned)word <= 127u);
    const bool out_ok = (lane >= 1) && (lane <= 30) && ((unsigned)word <= 127u);
    const bool wedge  = (sx == 0) && (lane == 1);       // image left edge word
    const bool eedge  = (sx == 4) && (word == 127);     // image right edge word

    const float* pb = pred + img * 3 * PLANE + word * 4;
    const float* tb = tru  + img * 3 * PLANE + word * 4;

    auto loadrow = [&](int j, float4* F) {
        const int gy = reflect512(r0 - 2 + j);
        const float* p = pb + gy * HW;
        const float* t = tb + gy * HW;
        if (ld_ok) {
            F[0] = *(const float4*)(p);
            F[1] = *(const float4*)(p + PLANE);
            F[2] = *(const float4*)(p + 2 * PLANE);
            F[3] = *(const float4*)(t);
            F[4] = *(const float4*)(t + PLANE);
            F[5] = *(const float4*)(t + 2 * PLANE);
        }
    };

    auto convrow = [&](const float4* F, unsigned& gP, unsigned& gT,
                       unsigned* rP, unsigned* rT) {
        {
            unsigned R0=q8i(F[0].x),R1=q8i(F[0].y),R2=q8i(F[0].z),R3=q8i(F[0].w);
            unsigned G0=q8i(F[1].x),G1=q8i(F[1].y),G2=q8i(F[1].z),G3=q8i(F[1].w);
            unsigned B0=q8i(F[2].x),B1=q8i(F[2].y),B2=q8i(F[2].z),B3=q8i(F[2].w);
            rP[0]=packq(R0,R1,R2,R3); rP[1]=packq(G0,G1,G2,G3); rP[2]=packq(B0,B1,B2,B3);
            gP = packq(gray1(R0,G0,B0), gray1(R1,G1,B1),
                       gray1(R2,G2,B2), gray1(R3,G3,B3));
        }
        {
            unsigned R0=q8i(F[3].x),R1=q8i(F[3].y),R2=q8i(F[3].z),R3=q8i(F[3].w);
            unsigned G0=q8i(F[4].x),G1=q8i(F[4].y),G2=q8i(F[4].z),G3=q8i(F[4].w);
            unsigned B0=q8i(F[5].x),B1=q8i(F[5].y),B2=q8i(F[5].z),B3=q8i(F[5].w);
            rT[0]=packq(R0,R1,R2,R3); rT[1]=packq(G0,G1,G2,G3); rT[2]=packq(B0,B1,B2,B3);
            gT = packq(gray1(R0,G0,B0), gray1(R1,G1,B1),
                       gray1(R2,G2,B2), gray1(R3,G3,B3));
        }
    };

    // sobel of the row held in gmid (gup/gdn: rows above/below), exact half-even.
    auto sobelrow = [&](unsigned gup, unsigned gmid, unsigned gdn) -> unsigned {
        const unsigned gp = __shfl_up_sync(0xFFFFFFFFu, gmid, 1);
        const unsigned gn = __shfl_down_sync(0xFFFFFFFFu, gmid, 1);
        unsigned W4 = __funnelshift_r(gp, gmid, 24);
        unsigned E4 = __funnelshift_r(gmid, gn, 8);
        if (wedge) W4 = __byte_perm(gmid, 0, 0x2101);   // reflect at x=0
        if (eedge) E4 = __byte_perm(gmid, 0, 0x2321);   // reflect at x=511
        const unsigned sx4 = __vabsdiffu4(E4, W4);
        const unsigned sy4 = __vabsdiffu4(gdn, gup);
        const unsigned avg = __vavgu4(sx4, sy4);
        const unsigned cor = (sx4 ^ sy4) & avg & 0x01010101u;
        return avg - cor;
    };

    auto dilmask = [&](unsigned vm) -> unsigned {
        const unsigned vp = __shfl_up_sync(0xFFFFFFFFu, vm, 1);
        const unsigned vn = __shfl_down_sync(0xFFFFFFFFu, vm, 1);
        unsigned Wv = __funnelshift_r(vp, vm, 24);
        unsigned Ev = __funnelshift_r(vm, vn, 8);
        if (wedge) Wv = __byte_perm(vm, 0, 0x2101);
        if (eedge) Ev = __byte_perm(vm, 0, 0x2321);
        return __vcmpgtu4(__vmaxu4(vm, __vmaxu4(Wv, Ev)), 0x0A0A0A0Au);
    };

    float4 Fc[6], Fn[6];
    unsigned gp1, gp2, gt1, gt2;         // gray rows j-2, j-1
    unsigned sp1, sp2, st1, st2;         // sobel rows j-3, j-2
    unsigned rpA[3], rpB[3], rpC[3];     // rgb pred rows j, j-1, j-2
    unsigned rtA[3], rtB[3], rtC[3];
    unsigned acc_s = 0, acc_e = 0;

    // ---- prologue: rows 0,1 ----
    loadrow(0, Fc);
    loadrow(1, Fn);
    convrow(Fc, gp1, gt1, rpC, rtC);                  // row 0
    #pragma unroll
    for (int q = 0; q < 6; q++) Fc[q] = Fn[q];
    loadrow(2, Fn);
    convrow(Fc, gp2, gt2, rpB, rtB);                  // row 1
    #pragma unroll
    for (int q = 0; q < 6; q++) Fc[q] = Fn[q];        // Fc = row 2

    // ---- j = 2,3: build sobel ring, no loss yet ----
    #pragma unroll
    for (int j = 2; j <= 3; ++j) {
        loadrow(j + 1, Fn);
        unsigned gnp, gnt;
        convrow(Fc, gnp, gnt, rpA, rtA);              // row j
        const unsigned snp = sobelrow(gp1, gp2, gnp); // sobel row j-1
        const unsigned snt = sobelrow(gt1, gt2, gnt);
        sp1 = sp2; sp2 = snp; st1 = st2; st2 = snt;
        gp1 = gp2; gp2 = gnp; gt1 = gt2; gt2 = gnt;
        #pragma unroll
        for (int c = 0; c < 3; c++) {
            rpC[c] = rpB[c]; rpB[c] = rpA[c];
            rtC[c] = rtB[c]; rtB[c] = rtA[c];
        }
        #pragma unroll
        for (int q = 0; q < 6; q++) Fc[q] = Fn[q];
    }

    // ---- steady loop: j = 4 .. SH+3, loss for image row r0 + j - 4 ----
    // FULL unroll: all ring indices become compile-time -> register renaming
    // deletes every Fc/Fn copy and ring shift (~36 MOVs/iter).
    #pragma unroll
    for (int j = 4; j <= SH + 3; ++j) {
        if (j < SH + 3) loadrow(j + 1, Fn);
        unsigned gnp, gnt;
        convrow(Fc, gnp, gnt, rpA, rtA);              // row j
        const unsigned snp = sobelrow(gp1, gp2, gnp); // sobel row j-1
        const unsigned snt = sobelrow(gt1, gt2, gnt);
        // vm row j-2 = max(sobel rows j-3, j-2, j-1)
        const unsigned vmp = __vmaxu4(sp1, __vmaxu4(sp2, snp));
        const unsigned vmt = __vmaxu4(st1, __vmaxu4(st2, snt));
        const unsigned kp = dilmask(vmp);
        const unsigned kt = dilmask(vmt);
        if (out_ok) {
            acc_s = __dp4a(__vabsdiffu4(sp2, st2), 0x01010101u, acc_s);
            const unsigned both = kp & kt;
            const unsigned onp  = kp & ~kt;
            const unsigned ont  = kt & ~kp;
            #pragma unroll
            for (int c = 0; c < 3; c++) {
                const unsigned val = (__vabsdiffu4(rpC[c], rtC[c]) & both) |
                                     (rpC[c] & onp) | (rtC[c] & ont);
                acc_e = __dp4a(val, 0x01010101u, acc_e);
            }
        }
        sp1 = sp2; sp2 = snp; st1 = st2; st2 = snt;
        gp1 = gp2; gp2 = gnp; gt1 = gt2; gt2 = gnt;
        #pragma unroll
        for (int c = 0; c < 3; c++) {
            rpC[c] = rpB[c]; rpB[c] = rpA[c];
            rtC[c] = rtB[c]; rtB[c] = rtA[c];
        }
        #pragma unroll
        for (int q = 0; q < 6; q++) Fc[q] = Fn[q];
    }

    // ---- exact integer reduction + last-block finalize ----
    const unsigned ws = __reduce_add_sync(0xFFFFFFFFu, acc_s);
    const unsigned we = __reduce_add_sync(0xFFFFFFFFu, acc_e);
    if (lane == 0) { s_red[wid] = ws; s_red[NWARPS + wid] = we; }
    __syncthreads();
    if (wid == 0) {
        unsigned a = (lane < NWARPS) ? s_red[lane] : 0u;
        unsigned e = (lane < NWARPS) ? s_red[NWARPS + lane] : 0u;
        a = __reduce_add_sync(0xFFFFFFFFu, a);
        e = __reduce_add_sync(0xFFFFFFFFu, e);
        if (lane == 0) {
            atomicAdd(&g_sum_sobel, (unsigned long long)a);
            atomicAdd(&g_sum_edge,  (unsigned long long)e);
            __threadfence();
            const unsigned old = atomicAdd(&g_count, 1u);
            if (old == NBLOCKS - 1) {
                const unsigned long long ss = atomicAdd(&g_sum_sobel, 0ULL);
                const unsigned long long se = atomicAdd(&g_sum_edge, 0ULL);
                const double N = 16.0 * 512.0 * 512.0;
                out[0] = (float)((double)ss / (255.0 * N));
                out[1] = (float)((double)se / (255.0 * N * 3.0));
                g_sum_sobel = 0ULL;
                g_sum_edge  = 0ULL;
                __threadfence();
                g_count = 0u;
            }
        }
    }
}

extern "C" void kernel_launch(void* const* d_in, const int* in_sizes, int n_in,
                              void* d_out, int out_size) {
    const float* y_pred = (const float*)d_in[0];
    const float* y_true = (const float*)d_in[1];
    float* out = (float*)d_out;

    cs_main_kernel<<<NBLOCKS, NTHREADS>>>(y_pred, y_true, out);
}